// round 13
// baseline (speedup 1.0000x reference)
#include <cuda_runtime.h>
#include <cstdint>

// Quantum autoencoder forward, batch=256. R13: one WARP per sample with the
// R11 telescoped math -> zero smem, zero block barriers, 5-shfl tail.
//
// Verified math (R6..R12): X-eigenbasis diagonal simulation; embedding+gates
// are 50 signed terms ang(x) = -1/2 sum_t alpha_t (-1)^{parity(rho_t . x)};
// GF(2) basis transform puts all 7 correlation masks into the low 3 bits of
// x', so the swap-test sum telescopes per 8-element group:
//   P(aux=1) = 0.5 - 2^-14 * sum_{groups} ( (sum_e re)^2 + (sum_e im)^2 )
//
// Layout: x' = lane*32 + j (j = 5 local bits). Each thread owns 4 complete
// correlation groups (j>>3). Per thread: 50 signed FADDs into C[32] (hi-sign
// from a 256B constexpr lane table), 5-stage WHT, 32 sincos, 4 telescopes,
// warp reduce, lane0 store. No inter-thread data exchange until the reduce.

#define NUM_Q 10
#define DEPTH 4
#define BATCH 256
#define TPB 64             // 2 warps = 2 samples per CTA; grid = 128
#define NGATES 40
#define NTERMS 50
#define FULLM 0xFFFFFFFFu

struct XForm {
    unsigned rho[NTERMS];   // transformed parity vectors (10 bits each)
};

__host__ __device__ constexpr int cpar(unsigned v) {
    int n = 0;
    while (v) { n ^= (int)(v & 1u); v >>= 1; }
    return n;
}

__host__ __device__ constexpr unsigned creduce(unsigned v, const unsigned* ech, int ne) {
    for (int i = 0; i < ne; ++i) {
        unsigned h = ech[i];
        unsigned m = 0x200u;
        while (m && !(h & m)) m >>= 1;
        if (v & m) v ^= h;
    }
    return v;
}

__host__ __device__ constexpr XForm make_xform() {
    // circuit Clifford tracking (identical to verified R6 code)
    unsigned lr[NUM_Q] = {}, kc[NUM_Q] = {};
    unsigned rg[NGATES] = {};
    for (int b = 0; b < NUM_Q; ++b) { lr[b] = 1u << b; kc[b] = 1u << b; }
    for (int l = 0; l < DEPTH; ++l) {
        for (int w = 0; w < NUM_Q; ++w) rg[l * NUM_Q + w] = lr[9 - w];
        for (int w = 0; w < NUM_Q; ++w) {
            const int cb = 9 - w;
            const int tb = (w < 9) ? (8 - w) : 9;
            lr[cb] ^= lr[tb];
            kc[tb] ^= kc[cb];
        }
    }
    // invcol = columns of T^{-1}: measurement columns kc0..kc2 first, extend
    unsigned invcol[NUM_Q] = {};
    unsigned ech[NUM_Q] = {};
    int ne = 0;
    for (int c = 0; c < 3; ++c) {
        invcol[c] = kc[c];
        ech[ne++] = creduce(kc[c], ech, ne);
    }
    int cnt = 3;
    for (int b = 0; b < NUM_Q && cnt < NUM_Q; ++b) {
        const unsigned v = 1u << b;
        const unsigned r = creduce(v, ech, ne);
        if (r) { invcol[cnt++] = v; ech[ne++] = r; }
    }
    XForm X{};
    for (int t = 0; t < NTERMS; ++t) {
        const unsigned old = (t < NUM_Q) ? (1u << t) : rg[t - NUM_Q];
        unsigned v = 0;
        for (int j = 0; j < NUM_Q; ++j)
            v |= (unsigned)cpar(old & invcol[j]) << j;
        X.rho[t] = v;
    }
    return X;
}

constexpr XForm TX = make_xform();

// per-lane (5 bits = x' bits 5..9) hi-sign table: bit t = parity((rho>>5)&lane)
struct PTab { unsigned long long p[32]; };

__host__ __device__ constexpr PTab make_ptab() {
    PTab t{};
    for (unsigned lane = 0; lane < 32; ++lane) {
        unsigned long long v = 0;
        for (int g = 0; g < NTERMS; ++g)
            v |= (unsigned long long)(unsigned)cpar((TX.rho[g] >> 5) & lane) << g;
        t.p[lane] = v;
    }
    return t;
}

__device__ const PTab d_ptab = make_ptab();

// ---- 50 signed terms into 32 group accumulators (group = rho & 31) ----
template<int T>
__device__ __forceinline__ void terms(float (&C)[32], const float (&fw)[NUM_Q],
                                      const float (&th)[NGATES],
                                      unsigned plo, unsigned phi) {
    if constexpr (T < NTERMS) {
        constexpr int m = (int)(TX.rho[T] & 31u);
        float alpha;
        if constexpr (T < NUM_Q) alpha = fw[9 - T];
        else                     alpha = th[T - NUM_Q];
        unsigned sgn;
        if constexpr (T < 32) sgn = (plo << (31 - T)) & 0x80000000u;
        else                  sgn = (phi << (63 - T)) & 0x80000000u;
        C[m] += __uint_as_float(__float_as_uint(alpha) ^ sgn);
        terms<T + 1>(C, fw, th, plo, phi);
    }
}

__global__ void __launch_bounds__(TPB, 1)
qae_kernel(const float* __restrict__ features,
           const float* __restrict__ weights,
           float* __restrict__ out)
{
    const int tid = threadIdx.x;
    const int lane = tid & 31;
    const int samp = blockIdx.x * (TPB / 32) + (tid >> 5);
    const float* f = features + samp * NUM_Q;

    // ---- front-load all memory (latencies overlap) ----
    const unsigned long long pm = d_ptab.p[lane];    // 256B table

    float fw[NUM_Q];
#pragma unroll
    for (int q = 0; q < NUM_Q / 2; ++q) {            // row stride 40B -> 8B aligned
        const float2 v = __ldg(reinterpret_cast<const float2*>(f) + q);
        fw[2 * q] = v.x; fw[2 * q + 1] = v.y;
    }
    float th[NGATES];
#pragma unroll
    for (int q = 0; q < NGATES / 4; ++q) {
        const float4 v = __ldg(reinterpret_cast<const float4*>(weights) + q);
        th[4 * q + 0] = v.x; th[4 * q + 1] = v.y;
        th[4 * q + 2] = v.z; th[4 * q + 3] = v.w;
    }

    const unsigned plo = (unsigned)pm;
    const unsigned phi = (unsigned)(pm >> 32);

    // 50 signed terms -> 32 group sums
    float C[32];
#pragma unroll
    for (int i = 0; i < 32; ++i) C[i] = 0.0f;
    terms<0>(C, fw, th, plo, phi);

    // 5-stage Walsh-Hadamard: ang[j] = sum_m (-1)^{popc(m&j)} C[m]
#pragma unroll
    for (int bit = 1; bit < 32; bit <<= 1) {
#pragma unroll
        for (int i = 0; i < 32; ++i) {
            if (!(i & bit)) {
                const float a = C[i], b = C[i | bit];
                C[i] = a + b;
                C[i | bit] = a - b;
            }
        }
    }

    // 4 complete correlation groups of 8 elements each; telescoped sums
    float q = 0.0f;
#pragma unroll
    for (int g = 0; g < 4; ++g) {
        float re[8], im[8];
#pragma unroll
        for (int e = 0; e < 8; ++e)
            __sincosf(-0.5f * C[g * 8 + e], &im[e], &re[e]);
        const float SR = ((re[0] + re[1]) + (re[2] + re[3]))
                       + ((re[4] + re[5]) + (re[6] + re[7]));
        const float SI = ((im[0] + im[1]) + (im[2] + im[3]))
                       + ((im[4] + im[5]) + (im[6] + im[7]));
        q = fmaf(SR, SR, fmaf(SI, SI, q));
    }

    // warp reduce; lane 0 writes
#pragma unroll
    for (int off = 16; off; off >>= 1)
        q += __shfl_xor_sync(FULLM, q, off);
    if (lane == 0)
        out[samp] = 0.5f - q * 6.103515625e-05f;     // 2^-14
}

extern "C" void kernel_launch(void* const* d_in, const int* in_sizes, int n_in,
                              void* d_out, int out_size)
{
    const float* features = (const float*)d_in[0];  // [256, 10]
    const float* weights  = (const float*)d_in[1];  // [4, 10]
    float* out = (float*)d_out;                     // [256]
    (void)in_sizes; (void)n_in; (void)out_size;

    qae_kernel<<<BATCH / (TPB / 32), TPB>>>(features, weights, out);
}